// round 7
// baseline (speedup 1.0000x reference)
#include <cuda_runtime.h>
#include <cuda_bf16.h>
#include <cstdint>

// QuantumLinear: B=4096, IN_F=1024, NQ=4, L=2, C=256 circuits.
// Closed-form <Z_q> via Heisenberg propagation (exact).
// R5: stage each block's contiguous 32KB x-chunk into SMEM with one
// cp.async.bulk (TMA) + mbarrier; coefficient prologue overlaps the fill;
// compute reads x via conflict-free LDS.128. Removes per-warp L2 latency.

static constexpr int NCIRC = 256;
static constexpr int ROWS  = 8;                       // batch rows per block
static constexpr unsigned XBYTES = ROWS * NCIRC * 16; // 32 KB

__global__ void __launch_bounds__(NCIRC) qfused_kernel(
    const float4* __restrict__ x,     // (B*256) float4
    const float4* __restrict__ w4,    // (256*2) float4
    float4* __restrict__ out)         // (B*256) float4
{
    __shared__ __align__(128) float4 sx[ROWS * NCIRC];   // 32 KB
    __shared__ __align__(8)  uint64_t mbar;

    const int c = threadIdx.x;                 // circuit 0..255
    const int base = blockIdx.x * ROWS * NCIRC;

    const uint32_t mbar_a = (uint32_t)__cvta_generic_to_shared(&mbar);
    const uint32_t sx_a   = (uint32_t)__cvta_generic_to_shared(sx);

    if (c == 0) {
        asm volatile("mbarrier.init.shared.b64 [%0], 1;" :: "r"(mbar_a) : "memory");
    }
    __syncthreads();
    if (c == 0) {
        asm volatile("mbarrier.arrive.expect_tx.shared.b64 _, [%0], %1;"
                     :: "r"(mbar_a), "r"(XBYTES) : "memory");
        asm volatile("cp.async.bulk.shared::cta.global.mbarrier::complete_tx::bytes "
                     "[%0], [%1], %2, [%3];"
                     :: "r"(sx_a), "l"(x + base), "r"(XBYTES), "r"(mbar_a)
                     : "memory");
    }

    // ---- per-circuit coefficients (overlap the bulk fill) ----
    const float4 w0 = w4[c * 2 + 0];           // alpha offsets
    const float4 w1 = w4[c * 2 + 1];           // beta angles
    float cb0, sb0, cb1, sb1, cb2, sb2, cb3, sb3;
    __sincosf(w1.x, &sb0, &cb0);
    __sincosf(w1.y, &sb1, &cb1);
    __sincosf(w1.z, &sb2, &cb2);
    __sincosf(w1.w, &sb3, &cb3);

    const float c1c2 = cb1 * cb2;
    const float s1s2 = sb1 * sb2;
    const float a0 = c1c2 * cb3, a1 = c1c2 * sb3;
    const float a2 = s1s2 * cb3, a3 = s1s2 * sb3;
    const float p0 = cb0 * cb1,  p1 = sb0 * sb1;
    const float d0 = cb0 * c1c2, d1 = cb0 * s1s2;
    const float e0 = cb0 * c1c2 * cb3;
    const float e1 = cb0 * s1s2 * sb3;
    const float e2 = sb0 * cb1 * sb2 * sb3;
    const float e3 = sb0 * sb1 * cb2 * cb3;

    // ---- wait for the staged x tile ----
    {
        uint32_t done;
        asm volatile(
            "{\n\t"
            ".reg .pred p;\n\t"
            "mbarrier.try_wait.parity.acquire.cta.shared::cta.b64 p, [%1], 0;\n\t"
            "selp.b32 %0, 1, 0, p;\n\t"
            "}"
            : "=r"(done) : "r"(mbar_a) : "memory");
        if (!done) {
            asm volatile(
                "{\n\t"
                ".reg .pred P1;\n\t"
                "WAIT_LOOP:\n\t"
                "mbarrier.try_wait.parity.acquire.cta.shared::cta.b64 P1, [%0], 0, 0x989680;\n\t"
                "@P1 bra.uni WAIT_DONE;\n\t"
                "bra.uni WAIT_LOOP;\n\t"
                "WAIT_DONE:\n\t"
                "}"
                :: "r"(mbar_a) : "memory");
        }
    }

    // ---- compute 8 rows from SMEM ----
#pragma unroll
    for (int r = 0; r < ROWS; r++) {
        const float4 xv = sx[r * NCIRC + c];

        float S0, C0, S1, C1, S2, C2, S3, C3;
        __sincosf(xv.x + w0.x, &S0, &C0);
        __sincosf(xv.y + w0.y, &S1, &C1);
        __sincosf(xv.z + w0.z, &S2, &C2);
        __sincosf(xv.w + w0.w, &S3, &C3);

        const float C1C3 = C1 * C3;
        const float S1S3 = S1 * S3;
        const float C0C2 = C0 * C2;
        const float S0S2 = S0 * S2;

        float4 z;
        z.x = fmaf(C1C3, fmaf(a0, C0, a3 * S0), S1S3 * fmaf(a1, S0, a2 * C0));
        z.y = C3 * fmaf(p0, C0C2, p1 * S0S2);
        z.z = fmaf(d0, C1C3, d1 * S1S3);
        z.w = fmaf(C2, fmaf(e0, C0, e1 * S0), S2 * fmaf(e2, C0, e3 * S0));

        out[base + r * NCIRC + c] = z;
    }
}

extern "C" void kernel_launch(void* const* d_in, const int* in_sizes, int n_in,
                              void* d_out, int out_size) {
    const float* x = (const float*)d_in[0];       // (4096, 1024) f32
    const float* w = (const float*)d_in[1];       // (256, 2, 4)  f32
    float* out = (float*)d_out;                   // (4096, 1024) f32

    const int B = 4096;
    qfused_kernel<<<B / ROWS, NCIRC>>>(
        (const float4*)x, (const float4*)w, (float4*)out);
}